// round 12
// baseline (speedup 1.0000x reference)
#include <cuda_runtime.h>
#include <cuda_fp16.h>
#include <math.h>
#include <stdint.h>

#define BB 128
#define HH 512
#define SS 2048
#define GRP 64                     // group 0 size (stream A)
#define HG  32                     // half-group size (streams B, C)

// Scratch (device globals: no allocations allowed)
__device__ __half g_Wh[HH * HH];                 // fp16 W_att
__device__ __half g_ah_h[(size_t)BB * HH * SS];  // fp16 copy of all_hidden
__device__ float g_u[BB][SS];
__device__ __half g_attn_h[BB][SS];
__device__ float g_context[BB][HH];
__device__ float g_h1[BB][HH];
__device__ float g_mlp_out[BB][HH];

__device__ __forceinline__ uint32_t smem_u32(const void* p) {
    uint32_t a;
    asm("{ .reg .u64 t; cvta.to.shared.u64 t, %1; cvt.u32.u64 %0, t; }" : "=r"(a) : "l"(p));
    return a;
}
__device__ __forceinline__ float tanh_fast(float x) {
    float y; asm("tanh.approx.f32 %0, %1;" : "=f"(y) : "f"(x)); return y;
}
__device__ __forceinline__ unsigned f2h2(float a, float b) {
    __half2 h = __floats2half2_rn(a, b);
    return *reinterpret_cast<unsigned*>(&h);
}

#define LDSM_X4(r0, r1, r2, r3, addr) \
    asm volatile("ldmatrix.sync.aligned.m8n8.x4.shared.b16 {%0,%1,%2,%3}, [%4];" \
        : "=r"(r0), "=r"(r1), "=r"(r2), "=r"(r3) : "r"(addr))
#define LDSM_X4_T(r0, r1, r2, r3, addr) \
    asm volatile("ldmatrix.sync.aligned.m8n8.x4.trans.shared.b16 {%0,%1,%2,%3}, [%4];" \
        : "=r"(r0), "=r"(r1), "=r"(r2), "=r"(r3) : "r"(addr))
#define MMA16816(c, a, b) \
    asm volatile("mma.sync.aligned.m16n8k16.row.col.f32.f16.f16.f32 " \
        "{%0,%1,%2,%3}, {%4,%5,%6,%7}, {%8,%9}, {%0,%1,%2,%3};" \
        : "+f"((c)[0]), "+f"((c)[1]), "+f"((c)[2]), "+f"((c)[3]) \
        : "r"((a)[0]), "r"((a)[1]), "r"((a)[2]), "r"((a)[3]), \
          "r"((b)[0]), "r"((b)[1]))
#define CP16(dst, src) \
    asm volatile("cp.async.cg.shared.global [%0], [%1], 16;" :: "r"(dst), "l"(src) : "memory")
#define CP_COMMIT() asm volatile("cp.async.commit_group;" ::: "memory")
#define CP_WAIT1()  asm volatile("cp.async.wait_group 1;" ::: "memory")

// ---------------------------------------------------------------------------
// Kernel 0: W fp32 -> fp16
// ---------------------------------------------------------------------------
__global__ __launch_bounds__(256) void wconv_kernel(const float* __restrict__ W) {
    int i = blockIdx.x * 256 + threadIdx.x;
    float4 v = ((const float4*)W)[i];
    ((uint2*)g_Wh)[i] = make_uint2(f2h2(v.x, v.y), f2h2(v.z, v.w));
}

// ---------------------------------------------------------------------------
// Kernel 1: scores + u.  CTA = (s-tile 64, b), 2 CTAs/SM.
// Warp tiling 4M x 2N (A ldmatrix dup 2x, B dup 4x -> 32KB smem reads/chunk).
// ---------------------------------------------------------------------------
#define STILE 64
#define ASTRIDE 80
#define BSTRIDE 144
#define ABUF (128 * ASTRIDE)
#define B_PANEL (512 * BSTRIDE)
#define A_OFF  B_PANEL
#define SU_OFF (A_OFF + 3 * ABUF)
#define K1_SMEM (SU_OFF + 256)

__global__ __launch_bounds__(256, 2) void scores_u_kernel(
    const float* __restrict__ ah, const float* __restrict__ v_att, int boff)
{
    extern __shared__ char smem[];
    const uint32_t sb = smem_u32(smem);
    const uint32_t sBb = sb;
    const uint32_t sAb = sb + A_OFF;
    float* su = (float*)(smem + SU_OFF);

    const int tid = threadIdx.x;
    const int wid = tid >> 5;
    const int lane = tid & 31;
    const int g = lane >> 2;
    const int t = lane & 3;
    const int warp_m = wid & 3;        // 4 warps over 128 rows (32 each)
    const int warp_n = wid >> 2;       // 2 warps over 64 cols (32 each)
    const int s0 = blockIdx.x * STILE;
    const int b = boff + blockIdx.y;

    const float* ahb = ah + (size_t)b * ((size_t)HH * SS);
    __half* ahh = g_ah_h + (size_t)b * ((size_t)HH * SS);

    const int lr = lane & 7, sel = lane >> 3;
    const uint32_t a_off = (uint32_t)((warp_m * 32 + (sel & 1) * 8 + lr) * ASTRIDE
                                      + (sel >> 1) * 16);
    const uint32_t b_off = (uint32_t)(((sel & 1) * 8 + lr) * BSTRIDE
                                      + (warp_n * 32 + (sel >> 1) * 8) * 2);

    if (tid < 64) su[tid] = 0.f;

    float ucol[8];
    #pragma unroll
    for (int i = 0; i < 8; i++) ucol[i] = 0.f;

    float4 pb[2];
    #pragma unroll
    for (int f = 0; f < 2; f++) {
        int idx = tid + f * 256; int kk = idx >> 4, q = idx & 15;
        pb[f] = *(const float4*)&ahb[(size_t)kk * SS + s0 + q * 4];
    }
    #pragma unroll
    for (int f = 0; f < 2; f++) {
        int idx = tid + f * 256; int kk = idx >> 4, q = idx & 15;
        uint2 hv = make_uint2(f2h2(pb[f].x, pb[f].y), f2h2(pb[f].z, pb[f].w));
        *(uint2*)(smem + kk * BSTRIDE + q * 8) = hv;
        *(uint2*)(ahh + (size_t)kk * SS + s0 + q * 4) = hv;
    }

    for (int ht = 0; ht < 4; ht++) {
        const int h0 = ht * 128;
        __syncthreads();
        #pragma unroll
        for (int c = 0; c < 2; c++) {
            #pragma unroll
            for (int f = 0; f < 2; f++) {
                int idx = tid + f * 256; int r = idx >> 2, q = idx & 3;
                CP16(sAb + c * ABUF + r * ASTRIDE + q * 16,
                     (const void*)(g_Wh + (size_t)(h0 + r) * HH + c * 32 + q * 8));
            }
            CP_COMMIT();
        }

        float acc[2][4][4];
        #pragma unroll
        for (int i = 0; i < 2; i++)
            #pragma unroll
            for (int j = 0; j < 4; j++)
                #pragma unroll
                for (int k = 0; k < 4; k++) acc[i][j][k] = 0.f;

        for (int i = 0; i < 16; i++) {
            CP_WAIT1();
            __syncthreads();
            if (ht == 0 && i + 1 < 16) {
                int k0 = (i + 1) * 32;
                #pragma unroll
                for (int f = 0; f < 2; f++) {
                    int idx = tid + f * 256; int kk = idx >> 4, q = idx & 15;
                    pb[f] = *(const float4*)&ahb[(size_t)(k0 + kk) * SS + s0 + q * 4];
                }
            }
            if (i + 2 < 16) {
                int c = i + 2;
                uint32_t slotb = sAb + (c % 3) * ABUF;
                #pragma unroll
                for (int f = 0; f < 2; f++) {
                    int idx = tid + f * 256; int r = idx >> 2, q = idx & 3;
                    CP16(slotb + r * ASTRIDE + q * 16,
                         (const void*)(g_Wh + (size_t)(h0 + r) * HH + c * 32 + q * 8));
                }
            }
            CP_COMMIT();
            // Compute chunk i (warp tile: 32 rows x 32 cols)
            {
                const uint32_t abase = sAb + (i % 3) * ABUF + a_off;
                const uint32_t bbase = sBb + (uint32_t)(i * 32) * BSTRIDE + b_off;
                #pragma unroll
                for (int kk = 0; kk < 2; kk++) {
                    uint32_t afr[2][4];
                    #pragma unroll
                    for (int ma = 0; ma < 2; ma++)
                        LDSM_X4(afr[ma][0], afr[ma][1], afr[ma][2], afr[ma][3],
                                abase + kk * 32 + ma * (16 * ASTRIDE));
                    uint32_t bfr[4][2];
                    #pragma unroll
                    for (int nb = 0; nb < 2; nb++)
                        LDSM_X4_T(bfr[2 * nb][0], bfr[2 * nb][1],
                                  bfr[2 * nb + 1][0], bfr[2 * nb + 1][1],
                                  bbase + kk * (16 * BSTRIDE) + nb * 32);
                    #pragma unroll
                    for (int ma = 0; ma < 2; ma++)
                        #pragma unroll
                        for (int na = 0; na < 4; na++)
                            MMA16816(acc[ma][na], afr[ma], bfr[na]);
                }
            }
            if (ht == 0 && i + 1 < 16) {
                int k0 = (i + 1) * 32;
                char* dst = smem + (size_t)(i + 1) * 32 * BSTRIDE;
                #pragma unroll
                for (int f = 0; f < 2; f++) {
                    int idx = tid + f * 256; int kk = idx >> 4, q = idx & 15;
                    uint2 hv = make_uint2(f2h2(pb[f].x, pb[f].y), f2h2(pb[f].z, pb[f].w));
                    *(uint2*)(dst + kk * BSTRIDE + q * 8) = hv;
                    *(uint2*)(ahh + (size_t)(k0 + kk) * SS + s0 + q * 4) = hv;
                }
            }
        }
        // Fold pass: tanh + v_att
        float vr[2][2];
        #pragma unroll
        for (int ma = 0; ma < 2; ma++) {
            int r = h0 + warp_m * 32 + ma * 16 + g;
            vr[ma][0] = __ldg(&v_att[r]);
            vr[ma][1] = __ldg(&v_att[r + 8]);
        }
        #pragma unroll
        for (int ma = 0; ma < 2; ma++)
            #pragma unroll
            for (int na = 0; na < 4; na++) {
                ucol[na * 2 + 0] += vr[ma][0] * tanh_fast(acc[ma][na][0])
                                  + vr[ma][1] * tanh_fast(acc[ma][na][2]);
                ucol[na * 2 + 1] += vr[ma][0] * tanh_fast(acc[ma][na][1])
                                  + vr[ma][1] * tanh_fast(acc[ma][na][3]);
            }
    }

    __syncthreads();
    #pragma unroll
    for (int na = 0; na < 4; na++) {
        atomicAdd(&su[warp_n * 32 + na * 8 + 2 * t + 0], ucol[na * 2 + 0]);
        atomicAdd(&su[warp_n * 32 + na * 8 + 2 * t + 1], ucol[na * 2 + 1]);
    }
    __syncthreads();
    if (tid < 64) g_u[b][s0 + tid] = su[tid];
}

// ---------------------------------------------------------------------------
// Kernel 2: softmax over s per batch; writes fp16 attn
// ---------------------------------------------------------------------------
__global__ __launch_bounds__(256) void softmax_kernel(int boff) {
    const int b = boff + blockIdx.x, tid = threadIdx.x;
    __shared__ float red[8];
    __shared__ float bcast;
    float v[8];
    #pragma unroll
    for (int i = 0; i < 8; i++) v[i] = g_u[b][tid + i * 256];
    float m = -INFINITY;
    #pragma unroll
    for (int i = 0; i < 8; i++) m = fmaxf(m, v[i]);
    #pragma unroll
    for (int o = 16; o; o >>= 1) m = fmaxf(m, __shfl_xor_sync(0xffffffffu, m, o));
    if ((tid & 31) == 0) red[tid >> 5] = m;
    __syncthreads();
    if (tid == 0) {
        float x = red[0];
        #pragma unroll
        for (int i = 1; i < 8; i++) x = fmaxf(x, red[i]);
        bcast = x;
    }
    __syncthreads();
    m = bcast;
    float sum = 0.f;
    #pragma unroll
    for (int i = 0; i < 8; i++) { v[i] = expf(v[i] - m); sum += v[i]; }
    #pragma unroll
    for (int o = 16; o; o >>= 1) sum += __shfl_xor_sync(0xffffffffu, sum, o);
    __syncthreads();
    if ((tid & 31) == 0) red[tid >> 5] = sum;
    __syncthreads();
    if (tid == 0) {
        float x = 0.f;
        #pragma unroll
        for (int i = 0; i < 8; i++) x += red[i];
        bcast = x;
    }
    __syncthreads();
    float inv = 1.f / bcast;
    #pragma unroll
    for (int i = 0; i < 8; i++)
        g_attn_h[b][tid + i * 256] = __float2half(v[i] * inv);
}

// ---------------------------------------------------------------------------
// Kernel 3: context[b][h] = sum_s attn[b][s]*ah_h[b][h][s]  (all fp16 reads)
// ---------------------------------------------------------------------------
__global__ __launch_bounds__(256) void context_kernel(int boff) {
    int gw = blockIdx.x * 8 + (threadIdx.x >> 5);
    int lane = threadIdx.x & 31;
    int b = boff + (gw >> 9), h = gw & 511;
    const uint4* a8 = reinterpret_cast<const uint4*>(
        g_ah_h + ((size_t)b * HH + h) * SS);
    const uint4* w8 = reinterpret_cast<const uint4*>(&g_attn_h[b][0]);
    float acc0 = 0.f, acc1 = 0.f;
    #pragma unroll
    for (int it = 0; it < 8; it++) {
        uint4 x = a8[it * 32 + lane];
        uint4 w = w8[it * 32 + lane];
        float2 fx, fw;
        fx = __half22float2(*(__half2*)&x.x); fw = __half22float2(*(__half2*)&w.x);
        acc0 += fx.x * fw.x + fx.y * fw.y;
        fx = __half22float2(*(__half2*)&x.y); fw = __half22float2(*(__half2*)&w.y);
        acc1 += fx.x * fw.x + fx.y * fw.y;
        fx = __half22float2(*(__half2*)&x.z); fw = __half22float2(*(__half2*)&w.z);
        acc0 += fx.x * fw.x + fx.y * fw.y;
        fx = __half22float2(*(__half2*)&x.w); fw = __half22float2(*(__half2*)&w.w);
        acc1 += fx.x * fw.x + fx.y * fw.y;
    }
    float acc = acc0 + acc1;
    #pragma unroll
    for (int o = 16; o; o >>= 1) acc += __shfl_xor_sync(0xffffffffu, acc, o);
    if (lane == 0) g_context[b][h] = acc;
}

// ---------------------------------------------------------------------------
// Kernel 4: out[b][j] = relu(in[b] . w[j] + bias[j])
// ---------------------------------------------------------------------------
__global__ __launch_bounds__(512) void linear_relu_kernel(
    int phase, const float* __restrict__ w, const float* __restrict__ bias, int boff)
{
    __shared__ float s_in[8][512];
    __shared__ float red[8][64];
    const int jt = blockIdx.x, bt = blockIdx.y;
    const int tid = threadIdx.x;
    const int bbase = boff + bt * 8;
    const float* in = phase ? &g_h1[0][0] : &g_context[0][0];
    float* out      = phase ? &g_mlp_out[0][0] : &g_h1[0][0];
    for (int t = tid; t < 8 * 128; t += 512) {
        int bb = t >> 7, q = t & 127;
        ((float4*)&s_in[bb][0])[q] = ((const float4*)&in[(size_t)(bbase + bb) * 512])[q];
    }
    const int j = jt * 64 + (tid & 63);
    const int ks = tid >> 6;
    float4 wreg[16];
    const float4* wr = (const float4*)&w[(size_t)j * 512 + ks * 64];
    #pragma unroll
    for (int q = 0; q < 16; q++) wreg[q] = wr[q];
    float bj = (ks == 0) ? bias[j] : 0.f;
    __syncthreads();
    #pragma unroll
    for (int bb = 0; bb < 8; bb++) {
        const float4* x = (const float4*)&s_in[bb][ks * 64];
        float acc = 0.f;
        #pragma unroll
        for (int q = 0; q < 16; q++) {
            float4 xx = x[q];
            acc += wreg[q].x * xx.x + wreg[q].y * xx.y
                 + wreg[q].z * xx.z + wreg[q].w * xx.w;
        }
        red[ks][tid & 63] = acc;
        __syncthreads();
        if (ks == 0) {
            float s = bj;
            #pragma unroll
            for (int k = 0; k < 8; k++) s += red[k][tid & 63];
            out[(size_t)(bbase + bb) * 512 + j] = fmaxf(s, 0.f);
        }
        __syncthreads();
    }
}

// ---------------------------------------------------------------------------
// Kernel 5: probs[b][s] = sum_h v_ptr[h]*tanh(ah_h[b][h][s] + out[b][h])
// ---------------------------------------------------------------------------
__global__ __launch_bounds__(256) void probs_kernel(
    const float* __restrict__ v_ptr, float* __restrict__ probs, int boff)
{
    __shared__ float s_o[512];
    __shared__ float s_v[512];
    const int tid = threadIdx.x;
    const int b = boff + blockIdx.y;
    const int s2 = blockIdx.x * 512 + tid * 2;
    s_o[tid] = g_mlp_out[b][tid];
    s_o[tid + 256] = g_mlp_out[b][tid + 256];
    s_v[tid] = v_ptr[tid];
    s_v[tid + 256] = v_ptr[tid + 256];
    __syncthreads();
    const __half* base = g_ah_h + (size_t)b * HH * SS + s2;
    float ax = 0.f, ay = 0.f;
    #pragma unroll 8
    for (int h = 0; h < 512; h++) {
        float2 f = __half22float2(*(const __half2*)(base + (size_t)h * SS));
        float o = s_o[h], v = s_v[h];
        ax += v * tanh_fast(f.x + o);
        ay += v * tanh_fast(f.y + o);
    }
    *(float2*)&probs[(size_t)b * SS + s2] = make_float2(ax, ay);
}

// ---------------------------------------------------------------------------
// One-time resources (created on first call = correctness run, before the
// harness's pre-capture baseline; reused on every later call).
// ---------------------------------------------------------------------------
static cudaStream_t s_strA = 0, s_strB = 0, s_strC = 0;
static cudaEvent_t s_evFork = 0, s_evJoin = 0;
static bool s_ready = false;

static void down_chain(cudaStream_t st, int boff, int nb,
                       const float* v_ptr, const float* fc1_w, const float* fc1_b,
                       const float* fc2_w, const float* fc2_b, float* probs)
{
    softmax_kernel<<<nb, 256, 0, st>>>(boff);
    context_kernel<<<(nb * HH) / 8, 256, 0, st>>>(boff);
    linear_relu_kernel<<<dim3(8, nb / 8), 512, 0, st>>>(0, fc1_w, fc1_b, boff);
    linear_relu_kernel<<<dim3(8, nb / 8), 512, 0, st>>>(1, fc2_w, fc2_b, boff);
    probs_kernel<<<dim3(SS / 512, nb), 256, 0, st>>>(v_ptr, probs, boff);
}

extern "C" void kernel_launch(void* const* d_in, const int* in_sizes, int n_in,
                              void* d_out, int out_size)
{
    const float* ah    = (const float*)d_in[0];
    const float* v_att = (const float*)d_in[1];
    const float* W_att = (const float*)d_in[2];
    const float* v_ptr = (const float*)d_in[3];
    const float* fc1_w = (const float*)d_in[4];
    const float* fc1_b = (const float*)d_in[5];
    const float* fc2_w = (const float*)d_in[6];
    const float* fc2_b = (const float*)d_in[7];
    float* probs = (float*)d_out;

    if (!s_ready) {
        cudaFuncSetAttribute(scores_u_kernel,
                             cudaFuncAttributeMaxDynamicSharedMemorySize, K1_SMEM);
        int prLo = 0, prHi = 0;
        cudaDeviceGetStreamPriorityRange(&prLo, &prHi);   // prHi = highest (most negative)
        int prMid = (prLo + prHi) / 2;
        cudaStreamCreateWithPriority(&s_strA, cudaStreamNonBlocking, prHi);
        cudaStreamCreateWithPriority(&s_strB, cudaStreamNonBlocking, prMid);
        cudaStreamCreateWithPriority(&s_strC, cudaStreamNonBlocking, prLo);
        cudaEventCreateWithFlags(&s_evFork, cudaEventDisableTiming);
        cudaEventCreateWithFlags(&s_evJoin, cudaEventDisableTiming);
        s_ready = true;
    }

    // Fork worker streams off the (possibly capturing) default stream.
    cudaEventRecord(s_evFork, 0);
    cudaStreamWaitEvent(s_strA, s_evFork, 0);
    wconv_kernel<<<HH * HH / 1024, 256, 0, s_strA>>>(W_att);
    cudaEventRecord(s_evFork, s_strA);
    cudaStreamWaitEvent(s_strB, s_evFork, 0);
    cudaStreamWaitEvent(s_strC, s_evFork, 0);

    // Group 0 (64 batches, highest priority): scores + downstream.
    scores_u_kernel<<<dim3(SS / STILE, GRP), 256, K1_SMEM, s_strA>>>(ah, v_att, 0);
    down_chain(s_strA, 0, GRP, v_ptr, fc1_w, fc1_b, fc2_w, fc2_b, probs);

    // Group 1a (32 batches, mid priority): finishes before 1b; its downstream
    // overlaps 1b's scores.
    scores_u_kernel<<<dim3(SS / STILE, HG), 256, K1_SMEM, s_strB>>>(ah, v_att, GRP);
    down_chain(s_strB, GRP, HG, v_ptr, fc1_w, fc1_b, fc2_w, fc2_b, probs);

    // Group 1b (32 batches, lowest priority): only its small downstream is exposed.
    scores_u_kernel<<<dim3(SS / STILE, HG), 256, K1_SMEM, s_strC>>>(ah, v_att, GRP + HG);
    down_chain(s_strC, GRP + HG, HG, v_ptr, fc1_w, fc1_b, fc2_w, fc2_b, probs);

    // Join all streams back into the default stream.
    cudaEventRecord(s_evJoin, s_strA);
    cudaStreamWaitEvent((cudaStream_t)0, s_evJoin, 0);
    cudaEventRecord(s_evJoin, s_strB);
    cudaStreamWaitEvent((cudaStream_t)0, s_evJoin, 0);
    cudaEventRecord(s_evJoin, s_strC);
    cudaStreamWaitEvent((cudaStream_t)0, s_evJoin, 0);
}

// round 13
// speedup vs baseline: 1.4935x; 1.4935x over previous
#include <cuda_runtime.h>
#include <cuda_fp16.h>
#include <math.h>
#include <stdint.h>

#define BB 128
#define HH 512
#define SS 2048
#define GRP0 96                    // group 0 (stream A, high priority)
#define GRP1 32                    // group 1 (stream B, low priority)

// Scratch (device globals: no allocations allowed)
__device__ __half g_Wh[HH * HH];                 // fp16 W_att
__device__ __half g_ah_h[(size_t)BB * HH * SS];  // fp16 copy of all_hidden
__device__ float g_u[BB][SS];
__device__ __half g_attn_h[BB][SS];
__device__ float g_context[BB][HH];
__device__ float g_h1[BB][HH];
__device__ float g_mlp_out[BB][HH];

__device__ __forceinline__ uint32_t smem_u32(const void* p) {
    uint32_t a;
    asm("{ .reg .u64 t; cvta.to.shared.u64 t, %1; cvt.u32.u64 %0, t; }" : "=r"(a) : "l"(p));
    return a;
}
__device__ __forceinline__ float tanh_fast(float x) {
    float y; asm("tanh.approx.f32 %0, %1;" : "=f"(y) : "f"(x)); return y;
}
__device__ __forceinline__ unsigned f2h2(float a, float b) {
    __half2 h = __floats2half2_rn(a, b);
    return *reinterpret_cast<unsigned*>(&h);
}

#define LDSM_X4(r0, r1, r2, r3, addr) \
    asm volatile("ldmatrix.sync.aligned.m8n8.x4.shared.b16 {%0,%1,%2,%3}, [%4];" \
        : "=r"(r0), "=r"(r1), "=r"(r2), "=r"(r3) : "r"(addr))
#define LDSM_X4_T(r0, r1, r2, r3, addr) \
    asm volatile("ldmatrix.sync.aligned.m8n8.x4.trans.shared.b16 {%0,%1,%2,%3}, [%4];" \
        : "=r"(r0), "=r"(r1), "=r"(r2), "=r"(r3) : "r"(addr))
#define MMA16816(c, a, b) \
    asm volatile("mma.sync.aligned.m16n8k16.row.col.f32.f16.f16.f32 " \
        "{%0,%1,%2,%3}, {%4,%5,%6,%7}, {%8,%9}, {%0,%1,%2,%3};" \
        : "+f"((c)[0]), "+f"((c)[1]), "+f"((c)[2]), "+f"((c)[3]) \
        : "r"((a)[0]), "r"((a)[1]), "r"((a)[2]), "r"((a)[3]), \
          "r"((b)[0]), "r"((b)[1]))
#define CP16(dst, src) \
    asm volatile("cp.async.cg.shared.global [%0], [%1], 16;" :: "r"(dst), "l"(src) : "memory")
#define CP_COMMIT() asm volatile("cp.async.commit_group;" ::: "memory")
#define CP_WAIT1()  asm volatile("cp.async.wait_group 1;" ::: "memory")

// ---------------------------------------------------------------------------
// Kernel 0: W fp32 -> fp16
// ---------------------------------------------------------------------------
__global__ __launch_bounds__(256) void wconv_kernel(const float* __restrict__ W) {
    int i = blockIdx.x * 256 + threadIdx.x;
    float4 v = ((const float4*)W)[i];
    ((uint2*)g_Wh)[i] = make_uint2(f2h2(v.x, v.y), f2h2(v.z, v.w));
}

// ---------------------------------------------------------------------------
// Kernel 1: scores + u.  CTA = (s-tile 64, b), 2 CTAs/SM.  (R11 exact)
// ---------------------------------------------------------------------------
#define STILE 64
#define ASTRIDE 80
#define BSTRIDE 144
#define ABUF (128 * ASTRIDE)
#define B_PANEL (512 * BSTRIDE)
#define A_OFF  B_PANEL
#define SU_OFF (A_OFF + 3 * ABUF)
#define K1_SMEM (SU_OFF + 256)

__global__ __launch_bounds__(256, 2) void scores_u_kernel(
    const float* __restrict__ ah, const float* __restrict__ v_att, int boff)
{
    extern __shared__ char smem[];
    const uint32_t sb = smem_u32(smem);
    const uint32_t sBb = sb;
    const uint32_t sAb = sb + A_OFF;
    float* su = (float*)(smem + SU_OFF);

    const int tid = threadIdx.x;
    const int wid = tid >> 5;
    const int lane = tid & 31;
    const int g = lane >> 2;
    const int t = lane & 3;
    const int warp_m = wid & 1;
    const int warp_n = wid >> 1;
    const int s0 = blockIdx.x * STILE;
    const int b = boff + blockIdx.y;

    const float* ahb = ah + (size_t)b * ((size_t)HH * SS);
    __half* ahh = g_ah_h + (size_t)b * ((size_t)HH * SS);

    const int lr = lane & 7, sel = lane >> 3;
    const uint32_t a_off = (uint32_t)((warp_m * 64 + (sel & 1) * 8 + lr) * ASTRIDE
                                      + (sel >> 1) * 16);
    const uint32_t b_off = (uint32_t)(((sel & 1) * 8 + lr) * BSTRIDE
                                      + (warp_n * 16 + (sel >> 1) * 8) * 2);

    if (tid < 64) su[tid] = 0.f;

    float ucol[4];
    #pragma unroll
    for (int i = 0; i < 4; i++) ucol[i] = 0.f;

    float4 pb[2];
    #pragma unroll
    for (int f = 0; f < 2; f++) {
        int idx = tid + f * 256; int kk = idx >> 4, q = idx & 15;
        pb[f] = *(const float4*)&ahb[(size_t)kk * SS + s0 + q * 4];
    }
    #pragma unroll
    for (int f = 0; f < 2; f++) {
        int idx = tid + f * 256; int kk = idx >> 4, q = idx & 15;
        uint2 hv = make_uint2(f2h2(pb[f].x, pb[f].y), f2h2(pb[f].z, pb[f].w));
        *(uint2*)(smem + kk * BSTRIDE + q * 8) = hv;
        *(uint2*)(ahh + (size_t)kk * SS + s0 + q * 4) = hv;
    }

    for (int ht = 0; ht < 4; ht++) {
        const int h0 = ht * 128;
        __syncthreads();
        #pragma unroll
        for (int c = 0; c < 2; c++) {
            #pragma unroll
            for (int f = 0; f < 2; f++) {
                int idx = tid + f * 256; int r = idx >> 2, q = idx & 3;
                CP16(sAb + c * ABUF + r * ASTRIDE + q * 16,
                     (const void*)(g_Wh + (size_t)(h0 + r) * HH + c * 32 + q * 8));
            }
            CP_COMMIT();
        }

        float acc[4][2][4];
        #pragma unroll
        for (int i = 0; i < 4; i++)
            #pragma unroll
            for (int j = 0; j < 2; j++)
                #pragma unroll
                for (int k = 0; k < 4; k++) acc[i][j][k] = 0.f;

        for (int i = 0; i < 16; i++) {
            CP_WAIT1();
            __syncthreads();
            if (ht == 0 && i + 1 < 16) {
                int k0 = (i + 1) * 32;
                #pragma unroll
                for (int f = 0; f < 2; f++) {
                    int idx = tid + f * 256; int kk = idx >> 4, q = idx & 15;
                    pb[f] = *(const float4*)&ahb[(size_t)(k0 + kk) * SS + s0 + q * 4];
                }
            }
            if (i + 2 < 16) {
                int c = i + 2;
                uint32_t slotb = sAb + (c % 3) * ABUF;
                #pragma unroll
                for (int f = 0; f < 2; f++) {
                    int idx = tid + f * 256; int r = idx >> 2, q = idx & 3;
                    CP16(slotb + r * ASTRIDE + q * 16,
                         (const void*)(g_Wh + (size_t)(h0 + r) * HH + c * 32 + q * 8));
                }
            }
            CP_COMMIT();
            {
                const uint32_t abase = sAb + (i % 3) * ABUF + a_off;
                const uint32_t bbase = sBb + (uint32_t)(i * 32) * BSTRIDE + b_off;
                #pragma unroll
                for (int kk = 0; kk < 2; kk++) {
                    uint32_t afr[4][4];
                    #pragma unroll
                    for (int ma = 0; ma < 4; ma++)
                        LDSM_X4(afr[ma][0], afr[ma][1], afr[ma][2], afr[ma][3],
                                abase + kk * 32 + ma * (16 * ASTRIDE));
                    uint32_t bfr[2][2];
                    LDSM_X4_T(bfr[0][0], bfr[0][1], bfr[1][0], bfr[1][1],
                              bbase + kk * (16 * BSTRIDE));
                    #pragma unroll
                    for (int ma = 0; ma < 4; ma++)
                        #pragma unroll
                        for (int na = 0; na < 2; na++)
                            MMA16816(acc[ma][na], afr[ma], bfr[na]);
                }
            }
            if (ht == 0 && i + 1 < 16) {
                int k0 = (i + 1) * 32;
                char* dst = smem + (size_t)(i + 1) * 32 * BSTRIDE;
                #pragma unroll
                for (int f = 0; f < 2; f++) {
                    int idx = tid + f * 256; int kk = idx >> 4, q = idx & 15;
                    uint2 hv = make_uint2(f2h2(pb[f].x, pb[f].y), f2h2(pb[f].z, pb[f].w));
                    *(uint2*)(dst + kk * BSTRIDE + q * 8) = hv;
                    *(uint2*)(ahh + (size_t)(k0 + kk) * SS + s0 + q * 4) = hv;
                }
            }
        }
        float vr[4][2];
        #pragma unroll
        for (int ma = 0; ma < 4; ma++) {
            int r = h0 + warp_m * 64 + ma * 16 + g;
            vr[ma][0] = __ldg(&v_att[r]);
            vr[ma][1] = __ldg(&v_att[r + 8]);
        }
        #pragma unroll
        for (int ma = 0; ma < 4; ma++)
            #pragma unroll
            for (int na = 0; na < 2; na++) {
                ucol[na * 2 + 0] += vr[ma][0] * tanh_fast(acc[ma][na][0])
                                  + vr[ma][1] * tanh_fast(acc[ma][na][2]);
                ucol[na * 2 + 1] += vr[ma][0] * tanh_fast(acc[ma][na][1])
                                  + vr[ma][1] * tanh_fast(acc[ma][na][3]);
            }
    }

    __syncthreads();
    #pragma unroll
    for (int na = 0; na < 2; na++) {
        atomicAdd(&su[warp_n * 16 + na * 8 + 2 * t + 0], ucol[na * 2 + 0]);
        atomicAdd(&su[warp_n * 16 + na * 8 + 2 * t + 1], ucol[na * 2 + 1]);
    }
    __syncthreads();
    if (tid < 64) g_u[b][s0 + tid] = su[tid];
}

// ---------------------------------------------------------------------------
// Kernel 2: softmax over s per batch; writes fp16 attn
// ---------------------------------------------------------------------------
__global__ __launch_bounds__(256) void softmax_kernel(int boff) {
    const int b = boff + blockIdx.x, tid = threadIdx.x;
    __shared__ float red[8];
    __shared__ float bcast;
    float v[8];
    #pragma unroll
    for (int i = 0; i < 8; i++) v[i] = g_u[b][tid + i * 256];
    float m = -INFINITY;
    #pragma unroll
    for (int i = 0; i < 8; i++) m = fmaxf(m, v[i]);
    #pragma unroll
    for (int o = 16; o; o >>= 1) m = fmaxf(m, __shfl_xor_sync(0xffffffffu, m, o));
    if ((tid & 31) == 0) red[tid >> 5] = m;
    __syncthreads();
    if (tid == 0) {
        float x = red[0];
        #pragma unroll
        for (int i = 1; i < 8; i++) x = fmaxf(x, red[i]);
        bcast = x;
    }
    __syncthreads();
    m = bcast;
    float sum = 0.f;
    #pragma unroll
    for (int i = 0; i < 8; i++) { v[i] = expf(v[i] - m); sum += v[i]; }
    #pragma unroll
    for (int o = 16; o; o >>= 1) sum += __shfl_xor_sync(0xffffffffu, sum, o);
    __syncthreads();
    if ((tid & 31) == 0) red[tid >> 5] = sum;
    __syncthreads();
    if (tid == 0) {
        float x = 0.f;
        #pragma unroll
        for (int i = 0; i < 8; i++) x += red[i];
        bcast = x;
    }
    __syncthreads();
    float inv = 1.f / bcast;
    #pragma unroll
    for (int i = 0; i < 8; i++)
        g_attn_h[b][tid + i * 256] = __float2half(v[i] * inv);
}

// ---------------------------------------------------------------------------
// Kernel 3: context[b][h] = sum_s attn[b][s]*ah_h[b][h][s]  (all fp16 reads)
// ---------------------------------------------------------------------------
__global__ __launch_bounds__(256) void context_kernel(int boff) {
    int gw = blockIdx.x * 8 + (threadIdx.x >> 5);
    int lane = threadIdx.x & 31;
    int b = boff + (gw >> 9), h = gw & 511;
    const uint4* a8 = reinterpret_cast<const uint4*>(
        g_ah_h + ((size_t)b * HH + h) * SS);
    const uint4* w8 = reinterpret_cast<const uint4*>(&g_attn_h[b][0]);
    float acc0 = 0.f, acc1 = 0.f;
    #pragma unroll
    for (int it = 0; it < 8; it++) {
        uint4 x = a8[it * 32 + lane];
        uint4 w = w8[it * 32 + lane];
        float2 fx, fw;
        fx = __half22float2(*(__half2*)&x.x); fw = __half22float2(*(__half2*)&w.x);
        acc0 += fx.x * fw.x + fx.y * fw.y;
        fx = __half22float2(*(__half2*)&x.y); fw = __half22float2(*(__half2*)&w.y);
        acc1 += fx.x * fw.x + fx.y * fw.y;
        fx = __half22float2(*(__half2*)&x.z); fw = __half22float2(*(__half2*)&w.z);
        acc0 += fx.x * fw.x + fx.y * fw.y;
        fx = __half22float2(*(__half2*)&x.w); fw = __half22float2(*(__half2*)&w.w);
        acc1 += fx.x * fw.x + fx.y * fw.y;
    }
    float acc = acc0 + acc1;
    #pragma unroll
    for (int o = 16; o; o >>= 1) acc += __shfl_xor_sync(0xffffffffu, acc, o);
    if (lane == 0) g_context[b][h] = acc;
}

// ---------------------------------------------------------------------------
// Kernel 4: out[b][j] = relu(in[b] . w[j] + bias[j])
// ---------------------------------------------------------------------------
__global__ __launch_bounds__(512) void linear_relu_kernel(
    int phase, const float* __restrict__ w, const float* __restrict__ bias, int boff)
{
    __shared__ float s_in[8][512];
    __shared__ float red[8][64];
    const int jt = blockIdx.x, bt = blockIdx.y;
    const int tid = threadIdx.x;
    const int bbase = boff + bt * 8;
    const float* in = phase ? &g_h1[0][0] : &g_context[0][0];
    float* out      = phase ? &g_mlp_out[0][0] : &g_h1[0][0];
    for (int t = tid; t < 8 * 128; t += 512) {
        int bb = t >> 7, q = t & 127;
        ((float4*)&s_in[bb][0])[q] = ((const float4*)&in[(size_t)(bbase + bb) * 512])[q];
    }
    const int j = jt * 64 + (tid & 63);
    const int ks = tid >> 6;
    float4 wreg[16];
    const float4* wr = (const float4*)&w[(size_t)j * 512 + ks * 64];
    #pragma unroll
    for (int q = 0; q < 16; q++) wreg[q] = wr[q];
    float bj = (ks == 0) ? bias[j] : 0.f;
    __syncthreads();
    #pragma unroll
    for (int bb = 0; bb < 8; bb++) {
        const float4* x = (const float4*)&s_in[bb][ks * 64];
        float acc = 0.f;
        #pragma unroll
        for (int q = 0; q < 16; q++) {
            float4 xx = x[q];
            acc += wreg[q].x * xx.x + wreg[q].y * xx.y
                 + wreg[q].z * xx.z + wreg[q].w * xx.w;
        }
        red[ks][tid & 63] = acc;
        __syncthreads();
        if (ks == 0) {
            float s = bj;
            #pragma unroll
            for (int k = 0; k < 8; k++) s += red[k][tid & 63];
            out[(size_t)(bbase + bb) * 512 + j] = fmaxf(s, 0.f);
        }
        __syncthreads();
    }
}

// ---------------------------------------------------------------------------
// Kernel 5: probs[b][s] = sum_h v_ptr[h]*tanh(ah_h[b][h][s] + out[b][h])
// ---------------------------------------------------------------------------
__global__ __launch_bounds__(256) void probs_kernel(
    const float* __restrict__ v_ptr, float* __restrict__ probs, int boff)
{
    __shared__ float s_o[512];
    __shared__ float s_v[512];
    const int tid = threadIdx.x;
    const int b = boff + blockIdx.y;
    const int s2 = blockIdx.x * 512 + tid * 2;
    s_o[tid] = g_mlp_out[b][tid];
    s_o[tid + 256] = g_mlp_out[b][tid + 256];
    s_v[tid] = v_ptr[tid];
    s_v[tid + 256] = v_ptr[tid + 256];
    __syncthreads();
    const __half* base = g_ah_h + (size_t)b * HH * SS + s2;
    float ax = 0.f, ay = 0.f;
    #pragma unroll 8
    for (int h = 0; h < 512; h++) {
        float2 f = __half22float2(*(const __half2*)(base + (size_t)h * SS));
        float o = s_o[h], v = s_v[h];
        ax += v * tanh_fast(f.x + o);
        ay += v * tanh_fast(f.y + o);
    }
    *(float2*)&probs[(size_t)b * SS + s2] = make_float2(ax, ay);
}

// ---------------------------------------------------------------------------
// One-time resources (created on first call = correctness run, before the
// harness's pre-capture baseline; reused on every later call).
// ---------------------------------------------------------------------------
static cudaStream_t s_strA = 0, s_strB = 0;
static cudaEvent_t s_evFork = 0, s_evJoin = 0;
static bool s_ready = false;

static void down_chain(cudaStream_t st, int boff, int nb,
                       const float* v_ptr, const float* fc1_w, const float* fc1_b,
                       const float* fc2_w, const float* fc2_b, float* probs)
{
    softmax_kernel<<<nb, 256, 0, st>>>(boff);
    context_kernel<<<(nb * HH) / 8, 256, 0, st>>>(boff);
    linear_relu_kernel<<<dim3(8, nb / 8), 512, 0, st>>>(0, fc1_w, fc1_b, boff);
    linear_relu_kernel<<<dim3(8, nb / 8), 512, 0, st>>>(1, fc2_w, fc2_b, boff);
    probs_kernel<<<dim3(SS / 512, nb), 256, 0, st>>>(v_ptr, probs, boff);
}

extern "C" void kernel_launch(void* const* d_in, const int* in_sizes, int n_in,
                              void* d_out, int out_size)
{
    const float* ah    = (const float*)d_in[0];
    const float* v_att = (const float*)d_in[1];
    const float* W_att = (const float*)d_in[2];
    const float* v_ptr = (const float*)d_in[3];
    const float* fc1_w = (const float*)d_in[4];
    const float* fc1_b = (const float*)d_in[5];
    const float* fc2_w = (const float*)d_in[6];
    const float* fc2_b = (const float*)d_in[7];
    float* probs = (float*)d_out;

    if (!s_ready) {
        cudaFuncSetAttribute(scores_u_kernel,
                             cudaFuncAttributeMaxDynamicSharedMemorySize, K1_SMEM);
        int prLo = 0, prHi = 0;
        cudaDeviceGetStreamPriorityRange(&prLo, &prHi);
        cudaStreamCreateWithPriority(&s_strA, cudaStreamNonBlocking, prHi);
        cudaStreamCreateWithPriority(&s_strB, cudaStreamNonBlocking, prLo);
        cudaEventCreateWithFlags(&s_evFork, cudaEventDisableTiming);
        cudaEventCreateWithFlags(&s_evJoin, cudaEventDisableTiming);
        s_ready = true;
    }

    // Fork both worker streams off the (possibly capturing) default stream.
    cudaEventRecord(s_evFork, 0);
    cudaStreamWaitEvent(s_strA, s_evFork, 0);
    wconv_kernel<<<HH * HH / 1024, 256, 0, s_strA>>>(W_att);
    cudaEventRecord(s_evFork, s_strA);
    cudaStreamWaitEvent(s_strB, s_evFork, 0);

    // Group 0 (96 batches, high priority): big scores + big downstream
    // (downstream hides under group 1's scores).
    scores_u_kernel<<<dim3(SS / STILE, GRP0), 256, K1_SMEM, s_strA>>>(ah, v_att, 0);
    down_chain(s_strA, 0, GRP0, v_ptr, fc1_w, fc1_b, fc2_w, fc2_b, probs);

    // Group 1 (32 batches, low priority): small exposed tail.
    scores_u_kernel<<<dim3(SS / STILE, GRP1), 256, K1_SMEM, s_strB>>>(ah, v_att, GRP0);
    down_chain(s_strB, GRP0, GRP1, v_ptr, fc1_w, fc1_b, fc2_w, fc2_b, probs);

    // Join both streams back into the default stream.
    cudaEventRecord(s_evJoin, s_strA);
    cudaStreamWaitEvent((cudaStream_t)0, s_evJoin, 0);
    cudaEventRecord(s_evJoin, s_strB);
    cudaStreamWaitEvent((cudaStream_t)0, s_evJoin, 0);
}

// round 14
// speedup vs baseline: 1.5059x; 1.0083x over previous
#include <cuda_runtime.h>
#include <cuda_fp16.h>
#include <math.h>
#include <stdint.h>

#define BB 128
#define HH 512
#define SS 2048
#define GRP 64                     // batches per stream group (2 groups)

// Scratch (device globals: no allocations allowed)
__device__ __half g_Wh[HH * HH];                 // fp16 W_att
__device__ __half g_ah_h[(size_t)BB * HH * SS];  // fp16 copy of all_hidden
__device__ float g_u[BB][SS];
__device__ __half g_attn_h[BB][SS];
__device__ float g_context[BB][HH];
__device__ float g_h1[BB][HH];
__device__ float g_mlp_out[BB][HH];

__device__ __forceinline__ uint32_t smem_u32(const void* p) {
    uint32_t a;
    asm("{ .reg .u64 t; cvta.to.shared.u64 t, %1; cvt.u32.u64 %0, t; }" : "=r"(a) : "l"(p));
    return a;
}
__device__ __forceinline__ float tanh_fast(float x) {
    float y; asm("tanh.approx.f32 %0, %1;" : "=f"(y) : "f"(x)); return y;
}
__device__ __forceinline__ unsigned f2h2(float a, float b) {
    __half2 h = __floats2half2_rn(a, b);
    return *reinterpret_cast<unsigned*>(&h);
}

#define LDSM_X4(r0, r1, r2, r3, addr) \
    asm volatile("ldmatrix.sync.aligned.m8n8.x4.shared.b16 {%0,%1,%2,%3}, [%4];" \
        : "=r"(r0), "=r"(r1), "=r"(r2), "=r"(r3) : "r"(addr))
#define LDSM_X4_T(r0, r1, r2, r3, addr) \
    asm volatile("ldmatrix.sync.aligned.m8n8.x4.trans.shared.b16 {%0,%1,%2,%3}, [%4];" \
        : "=r"(r0), "=r"(r1), "=r"(r2), "=r"(r3) : "r"(addr))
#define MMA16816(c, a, b) \
    asm volatile("mma.sync.aligned.m16n8k16.row.col.f32.f16.f16.f32 " \
        "{%0,%1,%2,%3}, {%4,%5,%6,%7}, {%8,%9}, {%0,%1,%2,%3};" \
        : "+f"((c)[0]), "+f"((c)[1]), "+f"((c)[2]), "+f"((c)[3]) \
        : "r"((a)[0]), "r"((a)[1]), "r"((a)[2]), "r"((a)[3]), \
          "r"((b)[0]), "r"((b)[1]))
#define CP16(dst, src) \
    asm volatile("cp.async.cg.shared.global [%0], [%1], 16;" :: "r"(dst), "l"(src) : "memory")
#define CP_COMMIT() asm volatile("cp.async.commit_group;" ::: "memory")
#define CP_WAIT1()  asm volatile("cp.async.wait_group 1;" ::: "memory")

// ---------------------------------------------------------------------------
// Kernel 0: W fp32 -> fp16
// ---------------------------------------------------------------------------
__global__ __launch_bounds__(256) void wconv_kernel(const float* __restrict__ W) {
    int i = blockIdx.x * 256 + threadIdx.x;
    float4 v = ((const float4*)W)[i];
    ((uint2*)g_Wh)[i] = make_uint2(f2h2(v.x, v.y), f2h2(v.z, v.w));
}

// ---------------------------------------------------------------------------
// Kernel 1: scores + u.  CTA = (s-tile 64, b), 2 CTAs/SM.  (R11 exact)
// ---------------------------------------------------------------------------
#define STILE 64
#define ASTRIDE 80
#define BSTRIDE 144
#define ABUF (128 * ASTRIDE)
#define B_PANEL (512 * BSTRIDE)
#define A_OFF  B_PANEL
#define SU_OFF (A_OFF + 3 * ABUF)
#define K1_SMEM (SU_OFF + 256)

__global__ __launch_bounds__(256, 2) void scores_u_kernel(
    const float* __restrict__ ah, const float* __restrict__ v_att, int boff)
{
    extern __shared__ char smem[];
    const uint32_t sb = smem_u32(smem);
    const uint32_t sBb = sb;
    const uint32_t sAb = sb + A_OFF;
    float* su = (float*)(smem + SU_OFF);

    const int tid = threadIdx.x;
    const int wid = tid >> 5;
    const int lane = tid & 31;
    const int g = lane >> 2;
    const int t = lane & 3;
    const int warp_m = wid & 1;
    const int warp_n = wid >> 1;
    const int s0 = blockIdx.x * STILE;
    const int b = boff + blockIdx.y;

    const float* ahb = ah + (size_t)b * ((size_t)HH * SS);
    __half* ahh = g_ah_h + (size_t)b * ((size_t)HH * SS);

    const int lr = lane & 7, sel = lane >> 3;
    const uint32_t a_off = (uint32_t)((warp_m * 64 + (sel & 1) * 8 + lr) * ASTRIDE
                                      + (sel >> 1) * 16);
    const uint32_t b_off = (uint32_t)(((sel & 1) * 8 + lr) * BSTRIDE
                                      + (warp_n * 16 + (sel >> 1) * 8) * 2);

    if (tid < 64) su[tid] = 0.f;

    float ucol[4];
    #pragma unroll
    for (int i = 0; i < 4; i++) ucol[i] = 0.f;

    float4 pb[2];
    #pragma unroll
    for (int f = 0; f < 2; f++) {
        int idx = tid + f * 256; int kk = idx >> 4, q = idx & 15;
        pb[f] = *(const float4*)&ahb[(size_t)kk * SS + s0 + q * 4];
    }
    #pragma unroll
    for (int f = 0; f < 2; f++) {
        int idx = tid + f * 256; int kk = idx >> 4, q = idx & 15;
        uint2 hv = make_uint2(f2h2(pb[f].x, pb[f].y), f2h2(pb[f].z, pb[f].w));
        *(uint2*)(smem + kk * BSTRIDE + q * 8) = hv;
        *(uint2*)(ahh + (size_t)kk * SS + s0 + q * 4) = hv;
    }

    for (int ht = 0; ht < 4; ht++) {
        const int h0 = ht * 128;
        __syncthreads();
        #pragma unroll
        for (int c = 0; c < 2; c++) {
            #pragma unroll
            for (int f = 0; f < 2; f++) {
                int idx = tid + f * 256; int r = idx >> 2, q = idx & 3;
                CP16(sAb + c * ABUF + r * ASTRIDE + q * 16,
                     (const void*)(g_Wh + (size_t)(h0 + r) * HH + c * 32 + q * 8));
            }
            CP_COMMIT();
        }

        float acc[4][2][4];
        #pragma unroll
        for (int i = 0; i < 4; i++)
            #pragma unroll
            for (int j = 0; j < 2; j++)
                #pragma unroll
                for (int k = 0; k < 4; k++) acc[i][j][k] = 0.f;

        for (int i = 0; i < 16; i++) {
            CP_WAIT1();
            __syncthreads();
            if (ht == 0 && i + 1 < 16) {
                int k0 = (i + 1) * 32;
                #pragma unroll
                for (int f = 0; f < 2; f++) {
                    int idx = tid + f * 256; int kk = idx >> 4, q = idx & 15;
                    pb[f] = *(const float4*)&ahb[(size_t)(k0 + kk) * SS + s0 + q * 4];
                }
            }
            if (i + 2 < 16) {
                int c = i + 2;
                uint32_t slotb = sAb + (c % 3) * ABUF;
                #pragma unroll
                for (int f = 0; f < 2; f++) {
                    int idx = tid + f * 256; int r = idx >> 2, q = idx & 3;
                    CP16(slotb + r * ASTRIDE + q * 16,
                         (const void*)(g_Wh + (size_t)(h0 + r) * HH + c * 32 + q * 8));
                }
            }
            CP_COMMIT();
            {
                const uint32_t abase = sAb + (i % 3) * ABUF + a_off;
                const uint32_t bbase = sBb + (uint32_t)(i * 32) * BSTRIDE + b_off;
                #pragma unroll
                for (int kk = 0; kk < 2; kk++) {
                    uint32_t afr[4][4];
                    #pragma unroll
                    for (int ma = 0; ma < 4; ma++)
                        LDSM_X4(afr[ma][0], afr[ma][1], afr[ma][2], afr[ma][3],
                                abase + kk * 32 + ma * (16 * ASTRIDE));
                    uint32_t bfr[2][2];
                    LDSM_X4_T(bfr[0][0], bfr[0][1], bfr[1][0], bfr[1][1],
                              bbase + kk * (16 * BSTRIDE));
                    #pragma unroll
                    for (int ma = 0; ma < 4; ma++)
                        #pragma unroll
                        for (int na = 0; na < 2; na++)
                            MMA16816(acc[ma][na], afr[ma], bfr[na]);
                }
            }
            if (ht == 0 && i + 1 < 16) {
                int k0 = (i + 1) * 32;
                char* dst = smem + (size_t)(i + 1) * 32 * BSTRIDE;
                #pragma unroll
                for (int f = 0; f < 2; f++) {
                    int idx = tid + f * 256; int kk = idx >> 4, q = idx & 15;
                    uint2 hv = make_uint2(f2h2(pb[f].x, pb[f].y), f2h2(pb[f].z, pb[f].w));
                    *(uint2*)(dst + kk * BSTRIDE + q * 8) = hv;
                    *(uint2*)(ahh + (size_t)(k0 + kk) * SS + s0 + q * 4) = hv;
                }
            }
        }
        float vr[4][2];
        #pragma unroll
        for (int ma = 0; ma < 4; ma++) {
            int r = h0 + warp_m * 64 + ma * 16 + g;
            vr[ma][0] = __ldg(&v_att[r]);
            vr[ma][1] = __ldg(&v_att[r + 8]);
        }
        #pragma unroll
        for (int ma = 0; ma < 4; ma++)
            #pragma unroll
            for (int na = 0; na < 2; na++) {
                ucol[na * 2 + 0] += vr[ma][0] * tanh_fast(acc[ma][na][0])
                                  + vr[ma][1] * tanh_fast(acc[ma][na][2]);
                ucol[na * 2 + 1] += vr[ma][0] * tanh_fast(acc[ma][na][1])
                                  + vr[ma][1] * tanh_fast(acc[ma][na][3]);
            }
    }

    __syncthreads();
    #pragma unroll
    for (int na = 0; na < 2; na++) {
        atomicAdd(&su[warp_n * 16 + na * 8 + 2 * t + 0], ucol[na * 2 + 0]);
        atomicAdd(&su[warp_n * 16 + na * 8 + 2 * t + 1], ucol[na * 2 + 1]);
    }
    __syncthreads();
    if (tid < 64) g_u[b][s0 + tid] = su[tid];
}

// ---------------------------------------------------------------------------
// Kernel 2: softmax over s per batch; writes fp16 attn
// ---------------------------------------------------------------------------
__global__ __launch_bounds__(256) void softmax_kernel(int boff) {
    const int b = boff + blockIdx.x, tid = threadIdx.x;
    __shared__ float red[8];
    __shared__ float bcast;
    float v[8];
    #pragma unroll
    for (int i = 0; i < 8; i++) v[i] = g_u[b][tid + i * 256];
    float m = -INFINITY;
    #pragma unroll
    for (int i = 0; i < 8; i++) m = fmaxf(m, v[i]);
    #pragma unroll
    for (int o = 16; o; o >>= 1) m = fmaxf(m, __shfl_xor_sync(0xffffffffu, m, o));
    if ((tid & 31) == 0) red[tid >> 5] = m;
    __syncthreads();
    if (tid == 0) {
        float x = red[0];
        #pragma unroll
        for (int i = 1; i < 8; i++) x = fmaxf(x, red[i]);
        bcast = x;
    }
    __syncthreads();
    m = bcast;
    float sum = 0.f;
    #pragma unroll
    for (int i = 0; i < 8; i++) { v[i] = expf(v[i] - m); sum += v[i]; }
    #pragma unroll
    for (int o = 16; o; o >>= 1) sum += __shfl_xor_sync(0xffffffffu, sum, o);
    __syncthreads();
    if ((tid & 31) == 0) red[tid >> 5] = sum;
    __syncthreads();
    if (tid == 0) {
        float x = 0.f;
        #pragma unroll
        for (int i = 0; i < 8; i++) x += red[i];
        bcast = x;
    }
    __syncthreads();
    float inv = 1.f / bcast;
    #pragma unroll
    for (int i = 0; i < 8; i++)
        g_attn_h[b][tid + i * 256] = __float2half(v[i] * inv);
}

// ---------------------------------------------------------------------------
// Kernel 3: context[b][h] = sum_s attn[b][s]*ah_h[b][h][s]  (all fp16 reads)
// ---------------------------------------------------------------------------
__global__ __launch_bounds__(256) void context_kernel(int boff) {
    int gw = blockIdx.x * 8 + (threadIdx.x >> 5);
    int lane = threadIdx.x & 31;
    int b = boff + (gw >> 9), h = gw & 511;
    const uint4* a8 = reinterpret_cast<const uint4*>(
        g_ah_h + ((size_t)b * HH + h) * SS);
    const uint4* w8 = reinterpret_cast<const uint4*>(&g_attn_h[b][0]);
    float acc0 = 0.f, acc1 = 0.f;
    #pragma unroll
    for (int it = 0; it < 8; it++) {
        uint4 x = a8[it * 32 + lane];
        uint4 w = w8[it * 32 + lane];
        float2 fx, fw;
        fx = __half22float2(*(__half2*)&x.x); fw = __half22float2(*(__half2*)&w.x);
        acc0 += fx.x * fw.x + fx.y * fw.y;
        fx = __half22float2(*(__half2*)&x.y); fw = __half22float2(*(__half2*)&w.y);
        acc1 += fx.x * fw.x + fx.y * fw.y;
        fx = __half22float2(*(__half2*)&x.z); fw = __half22float2(*(__half2*)&w.z);
        acc0 += fx.x * fw.x + fx.y * fw.y;
        fx = __half22float2(*(__half2*)&x.w); fw = __half22float2(*(__half2*)&w.w);
        acc1 += fx.x * fw.x + fx.y * fw.y;
    }
    float acc = acc0 + acc1;
    #pragma unroll
    for (int o = 16; o; o >>= 1) acc += __shfl_xor_sync(0xffffffffu, acc, o);
    if (lane == 0) g_context[b][h] = acc;
}

// ---------------------------------------------------------------------------
// Kernel 4: out[b][j] = relu(in[b] . w[j] + bias[j])
// ---------------------------------------------------------------------------
__global__ __launch_bounds__(512) void linear_relu_kernel(
    int phase, const float* __restrict__ w, const float* __restrict__ bias, int boff)
{
    __shared__ float s_in[8][512];
    __shared__ float red[8][64];
    const int jt = blockIdx.x, bt = blockIdx.y;
    const int tid = threadIdx.x;
    const int bbase = boff + bt * 8;
    const float* in = phase ? &g_h1[0][0] : &g_context[0][0];
    float* out      = phase ? &g_mlp_out[0][0] : &g_h1[0][0];
    for (int t = tid; t < 8 * 128; t += 512) {
        int bb = t >> 7, q = t & 127;
        ((float4*)&s_in[bb][0])[q] = ((const float4*)&in[(size_t)(bbase + bb) * 512])[q];
    }
    const int j = jt * 64 + (tid & 63);
    const int ks = tid >> 6;
    float4 wreg[16];
    const float4* wr = (const float4*)&w[(size_t)j * 512 + ks * 64];
    #pragma unroll
    for (int q = 0; q < 16; q++) wreg[q] = wr[q];
    float bj = (ks == 0) ? bias[j] : 0.f;
    __syncthreads();
    #pragma unroll
    for (int bb = 0; bb < 8; bb++) {
        const float4* x = (const float4*)&s_in[bb][ks * 64];
        float acc = 0.f;
        #pragma unroll
        for (int q = 0; q < 16; q++) {
            float4 xx = x[q];
            acc += wreg[q].x * xx.x + wreg[q].y * xx.y
                 + wreg[q].z * xx.z + wreg[q].w * xx.w;
        }
        red[ks][tid & 63] = acc;
        __syncthreads();
        if (ks == 0) {
            float s = bj;
            #pragma unroll
            for (int k = 0; k < 8; k++) s += red[k][tid & 63];
            out[(size_t)(bbase + bb) * 512 + j] = fmaxf(s, 0.f);
        }
        __syncthreads();
    }
}

// ---------------------------------------------------------------------------
// Kernel 5: probs[b][s] = sum_h v_ptr[h]*tanh(ah_h[b][h][s] + out[b][h])
// 128-thread CTAs, 256 s per CTA (2 per thread via half2) -> 2x CTA count
// for better latency hiding when a small tail group runs alone.
// ---------------------------------------------------------------------------
__global__ __launch_bounds__(128) void probs_kernel(
    const float* __restrict__ v_ptr, float* __restrict__ probs, int boff)
{
    __shared__ float s_o[512];
    __shared__ float s_v[512];
    const int tid = threadIdx.x;
    const int b = boff + blockIdx.y;
    const int s2 = blockIdx.x * 256 + tid * 2;
    #pragma unroll
    for (int i = 0; i < 4; i++) {
        s_o[tid + i * 128] = g_mlp_out[b][tid + i * 128];
        s_v[tid + i * 128] = v_ptr[tid + i * 128];
    }
    __syncthreads();
    const __half* base = g_ah_h + (size_t)b * HH * SS + s2;
    float ax = 0.f, ay = 0.f;
    #pragma unroll 8
    for (int h = 0; h < 512; h++) {
        float2 f = __half22float2(*(const __half2*)(base + (size_t)h * SS));
        float o = s_o[h], v = s_v[h];
        ax += v * tanh_fast(f.x + o);
        ay += v * tanh_fast(f.y + o);
    }
    *(float2*)&probs[(size_t)b * SS + s2] = make_float2(ax, ay);
}

// ---------------------------------------------------------------------------
// One-time resources (created on first call = correctness run, before the
// harness's pre-capture baseline; reused on every later call).
// ---------------------------------------------------------------------------
static cudaStream_t s_strA = 0, s_strB = 0;
static cudaEvent_t s_evFork = 0, s_evJoin = 0;
static bool s_ready = false;

static void down_chain(cudaStream_t st, int boff, int nb,
                       const float* v_ptr, const float* fc1_w, const float* fc1_b,
                       const float* fc2_w, const float* fc2_b, float* probs)
{
    softmax_kernel<<<nb, 256, 0, st>>>(boff);
    context_kernel<<<(nb * HH) / 8, 256, 0, st>>>(boff);
    linear_relu_kernel<<<dim3(8, nb / 8), 512, 0, st>>>(0, fc1_w, fc1_b, boff);
    linear_relu_kernel<<<dim3(8, nb / 8), 512, 0, st>>>(1, fc2_w, fc2_b, boff);
    probs_kernel<<<dim3(SS / 256, nb), 128, 0, st>>>(v_ptr, probs, boff);
}

extern "C" void kernel_launch(void* const* d_in, const int* in_sizes, int n_in,
                              void* d_out, int out_size)
{
    const float* ah    = (const float*)d_in[0];
    const float* v_att = (const float*)d_in[1];
    const float* W_att = (const float*)d_in[2];
    const float* v_ptr = (const float*)d_in[3];
    const float* fc1_w = (const float*)d_in[4];
    const float* fc1_b = (const float*)d_in[5];
    const float* fc2_w = (const float*)d_in[6];
    const float* fc2_b = (const float*)d_in[7];
    float* probs = (float*)d_out;

    if (!s_ready) {
        cudaFuncSetAttribute(scores_u_kernel,
                             cudaFuncAttributeMaxDynamicSharedMemorySize, K1_SMEM);
        int prLo = 0, prHi = 0;
        cudaDeviceGetStreamPriorityRange(&prLo, &prHi);
        cudaStreamCreateWithPriority(&s_strA, cudaStreamNonBlocking, prHi);
        cudaStreamCreateWithPriority(&s_strB, cudaStreamNonBlocking, prLo);
        cudaEventCreateWithFlags(&s_evFork, cudaEventDisableTiming);
        cudaEventCreateWithFlags(&s_evJoin, cudaEventDisableTiming);
        s_ready = true;
    }

    // Fork both worker streams off the (possibly capturing) default stream.
    cudaEventRecord(s_evFork, 0);
    cudaStreamWaitEvent(s_strA, s_evFork, 0);
    wconv_kernel<<<HH * HH / 1024, 256, 0, s_strA>>>(W_att);
    cudaEventRecord(s_evFork, s_strA);
    cudaStreamWaitEvent(s_strB, s_evFork, 0);

    // Group 0 (64 batches, high priority).
    scores_u_kernel<<<dim3(SS / STILE, GRP), 256, K1_SMEM, s_strA>>>(ah, v_att, 0);
    down_chain(s_strA, 0, GRP, v_ptr, fc1_w, fc1_b, fc2_w, fc2_b, probs);

    // Group 1 (64 batches, low priority — downstream overlaps group-0 work).
    scores_u_kernel<<<dim3(SS / STILE, GRP), 256, K1_SMEM, s_strB>>>(ah, v_att, GRP);
    down_chain(s_strB, GRP, GRP, v_ptr, fc1_w, fc1_b, fc2_w, fc2_b, probs);

    // Join both streams back into the default stream.
    cudaEventRecord(s_evJoin, s_strA);
    cudaStreamWaitEvent((cudaStream_t)0, s_evJoin, 0);
    cudaEventRecord(s_evJoin, s_strB);
    cudaStreamWaitEvent((cudaStream_t)0, s_evJoin, 0);
}